// round 4
// baseline (speedup 1.0000x reference)
#include <cuda_runtime.h>
#include <math.h>

// Problem constants (fixed shapes from reference: B=8, S=4096, D=1024, H=16, hd=64)
#define MTOT  32768          // B*S
#define DDIM  1024
#define N_QKV 3072           // 3*D
#define NHEAD 16
#define HDIM  64

// Scratch (static device globals — allocation-free per harness rules)
__device__ float g_qkv[(size_t)MTOT * N_QKV];   // 384 MB
__device__ float g_attn[(size_t)MTOT * DDIM];   // 128 MB

// ---------------------------------------------------------------------------
// SIMT fp32 GEMM with fused bias: C[M,N] = A[M,K] @ B[K,N] + bias[N]
// BM=128, BN=128, BK=8, TM=TN=8, 256 threads. All dims divisible -> no guards.
// ---------------------------------------------------------------------------
template<int BM, int BN, int BK, int TM, int TN>
__global__ __launch_bounds__((BM / TM) * (BN / TN))
void sgemm_bias_kernel(int M, int N, int K,
                       const float* __restrict__ A,
                       const float* __restrict__ B,
                       const float* __restrict__ bias,
                       float* __restrict__ C)
{
    __shared__ float As[BK][BM];
    __shared__ float Bs[BK][BN];

    const int tid = threadIdx.x;
    const int bx = blockIdx.x;   // N tiles
    const int by = blockIdx.y;   // M tiles

    const int tx = tid % (BN / TN);   // 0..15
    const int ty = tid / (BN / TN);   // 0..15

    // A tile load mapping: BM*BK = 1024 floats = 256 threads * float4
    const int aRow  = tid / (BK / 4);   // 0..127
    const int aCol4 = tid % (BK / 4);   // 0..1
    // B tile load mapping: BK*BN = 1024 floats = 256 threads * float4
    const int bRow  = tid / (BN / 4);   // 0..7
    const int bCol4 = tid % (BN / 4);   // 0..31

    const float* Ablk = A + (size_t)(by * BM) * K;
    const float* Bblk = B + (size_t)(bx * BN);

    float acc[TM][TN];
    #pragma unroll
    for (int i = 0; i < TM; i++)
        #pragma unroll
        for (int j = 0; j < TN; j++) acc[i][j] = 0.0f;

    for (int k0 = 0; k0 < K; k0 += BK) {
        // Load A tile (transposed into smem for conflict-free frag reads)
        float4 a4 = *reinterpret_cast<const float4*>(
            Ablk + (size_t)aRow * K + k0 + aCol4 * 4);
        As[aCol4 * 4 + 0][aRow] = a4.x;
        As[aCol4 * 4 + 1][aRow] = a4.y;
        As[aCol4 * 4 + 2][aRow] = a4.z;
        As[aCol4 * 4 + 3][aRow] = a4.w;
        // Load B tile
        *reinterpret_cast<float4*>(&Bs[bRow][bCol4 * 4]) =
            *reinterpret_cast<const float4*>(
                Bblk + (size_t)(k0 + bRow) * N + bCol4 * 4);
        __syncthreads();

        #pragma unroll
        for (int k = 0; k < BK; k++) {
            float ar[TM], br[TN];
            *reinterpret_cast<float4*>(&ar[0]) =
                *reinterpret_cast<const float4*>(&As[k][ty * TM]);
            *reinterpret_cast<float4*>(&ar[4]) =
                *reinterpret_cast<const float4*>(&As[k][ty * TM + 4]);
            *reinterpret_cast<float4*>(&br[0]) =
                *reinterpret_cast<const float4*>(&Bs[k][tx * TN]);
            *reinterpret_cast<float4*>(&br[4]) =
                *reinterpret_cast<const float4*>(&Bs[k][tx * TN + 4]);
            #pragma unroll
            for (int i = 0; i < TM; i++)
                #pragma unroll
                for (int j = 0; j < TN; j++)
                    acc[i][j] = fmaf(ar[i], br[j], acc[i][j]);
        }
        __syncthreads();
    }

    // Epilogue: add bias, vectorized store
    float bsv[TN];
    #pragma unroll
    for (int j = 0; j < TN; j++)
        bsv[j] = bias[bx * BN + tx * TN + j];

    float* Cblk = C + (size_t)(by * BM) * N + bx * BN;
    #pragma unroll
    for (int i = 0; i < TM; i++) {
        float* crow = Cblk + (size_t)(ty * TM + i) * N + tx * TN;
        #pragma unroll
        for (int j = 0; j < TN; j += 4) {
            float4 v;
            v.x = acc[i][j + 0] + bsv[j + 0];
            v.y = acc[i][j + 1] + bsv[j + 1];
            v.z = acc[i][j + 2] + bsv[j + 2];
            v.w = acc[i][j + 3] + bsv[j + 3];
            *reinterpret_cast<float4*>(crow + j) = v;
        }
    }
}

// ---------------------------------------------------------------------------
// Per-token cross-head attention (16x16 softmax attention within each token).
// qkv row layout: [H=16][q:64 | k:64 | v:64]. One block of 128 threads / token.
// ---------------------------------------------------------------------------
__global__ __launch_bounds__(128)
void attn_kernel(const float* __restrict__ qkv, float* __restrict__ out)
{
    __shared__ float row[N_QKV];        // 12 KB
    __shared__ float sc[NHEAD][NHEAD + 1];

    const int t = threadIdx.x;
    const size_t tok = blockIdx.x;
    const float* src = qkv + tok * (size_t)N_QKV;

    // Load full qkv row (vectorized, coalesced)
    const float4* s4 = reinterpret_cast<const float4*>(src);
    float4* r4 = reinterpret_cast<float4*>(row);
    #pragma unroll
    for (int i = t; i < N_QKV / 4; i += 128) r4[i] = s4[i];
    __syncthreads();

    // Scores: 256 (qh,kh) pairs, 2 per thread
    #pragma unroll
    for (int p = t; p < NHEAD * NHEAD; p += 128) {
        const int qh = p >> 4;
        const int kh = p & 15;
        const float* q  = row + qh * 192;
        const float* kk = row + kh * 192 + 64;
        float s = 0.0f;
        #pragma unroll
        for (int d = 0; d < HDIM; d++) s = fmaf(q[d], kk[d], s);
        sc[qh][kh] = s * 0.125f;   // 1/sqrt(64)
    }
    __syncthreads();

    // Row softmax (threads 0..15, one row each)
    if (t < NHEAD) {
        float m = sc[t][0];
        #pragma unroll
        for (int j = 1; j < NHEAD; j++) m = fmaxf(m, sc[t][j]);
        float sum = 0.0f;
        #pragma unroll
        for (int j = 0; j < NHEAD; j++) {
            float e = __expf(sc[t][j] - m);
            sc[t][j] = e;
            sum += e;
        }
        float inv = 1.0f / sum;
        #pragma unroll
        for (int j = 0; j < NHEAD; j++) sc[t][j] *= inv;
    }
    __syncthreads();

    // Output: out[qh*64+d] = sum_kh sc[qh][kh] * v[kh][d]; 8 outputs/thread
    float* dst = out + tok * (size_t)DDIM;
    #pragma unroll
    for (int o = t; o < DDIM; o += 128) {
        const int qh = o >> 6;
        const int d  = o & 63;
        float a = 0.0f;
        #pragma unroll
        for (int kh = 0; kh < NHEAD; kh++)
            a = fmaf(sc[qh][kh], row[kh * 192 + 128 + d], a);
        dst[o] = a;
    }
}

// ---------------------------------------------------------------------------
// Launch: GEMM1(qkv) -> attention -> GEMM2(out). Same stream, graph-capturable.
// ---------------------------------------------------------------------------
extern "C" void kernel_launch(void* const* d_in, const int* in_sizes, int n_in,
                              void* d_out, int out_size)
{
    (void)in_sizes; (void)n_in; (void)out_size;
    const float* x     = (const float*)d_in[0];
    const float* W_qkv = (const float*)d_in[1];
    const float* b_qkv = (const float*)d_in[2];
    const float* W_out = (const float*)d_in[3];
    const float* b_out = (const float*)d_in[4];
    float* out = (float*)d_out;

    void* p_qkv = nullptr;
    void* p_att = nullptr;
    cudaGetSymbolAddress(&p_qkv, g_qkv);
    cudaGetSymbolAddress(&p_att, g_attn);
    float* qkv = (float*)p_qkv;
    float* att = (float*)p_att;

    // GEMM1: [32768,1024] @ [1024,3072] + b_qkv
    {
        dim3 grid(N_QKV / 128, MTOT / 128);
        sgemm_bias_kernel<128, 128, 8, 8, 8><<<grid, 256>>>(
            MTOT, N_QKV, DDIM, x, W_qkv, b_qkv, qkv);
    }
    // Per-token 16x16 attention
    attn_kernel<<<MTOT, 128>>>(qkv, att);
    // GEMM2: [32768,1024] @ [1024,1024] + b_out
    {
        dim3 grid(DDIM / 128, MTOT / 128);
        sgemm_bias_kernel<128, 128, 8, 8, 8><<<grid, 256>>>(
            MTOT, DDIM, DDIM, att, W_out, b_out, out);
    }
}

// round 10
// speedup vs baseline: 2.9500x; 2.9500x over previous
#include <cuda_runtime.h>
#include <cuda_fp16.h>
#include <math.h>
#include <stdint.h>

// Fixed shapes: B=8, S=4096, D=1024, H=16, hd=64
#define MTOT  32768
#define DDIM  1024
#define N_QKV 3072
#define NHEAD 16
#define HDIM  64

// GEMM tiling: BM=BN=128, BK=32, 8 warps, 2-stage cp.async
#define ROW_B   80        // padded smem row: 40 halves = 80 bytes (conflict-free)
#define ATILE_B (128 * ROW_B)        // 10240
#define STAGE_B (2 * ATILE_B)        // 20480 (A tile + B tile)

// ---------------- scratch (device globals; allocation-free) ----------------
__device__ __align__(16) __half g_xh  [(size_t)MTOT * DDIM];    // 64 MB
__device__ __align__(16) __half g_qkv [(size_t)MTOT * N_QKV];   // 192 MB
__device__ __align__(16) __half g_ah  [(size_t)MTOT * DDIM];    // 64 MB
__device__ __align__(16) __half g_wqh [(size_t)N_QKV * DDIM];   // [N,K] 6 MB
__device__ __align__(16) __half g_woh [(size_t)DDIM * DDIM];    // [N,K] 2 MB

// ---------------- PTX helpers (sm_80-level only; no 'a' features) ----------
__device__ __forceinline__ uint32_t smem_u32(const void* p) {
    uint32_t a;
    asm("{ .reg .u64 t; cvta.to.shared.u64 t, %1; cvt.u32.u64 %0, t; }"
        : "=r"(a) : "l"(p));
    return a;
}
__device__ __forceinline__ void cp16(uint32_t dst, const void* src) {
    asm volatile("cp.async.cg.shared.global [%0], [%1], 16;"
                 :: "r"(dst), "l"(src) : "memory");
}
#define CP_COMMIT() asm volatile("cp.async.commit_group;" ::: "memory")
#define CP_WAIT(n)  asm volatile("cp.async.wait_group %0;" :: "n"(n) : "memory")

#define LDSM_X4(r, addr) \
    asm volatile("ldmatrix.sync.aligned.m8n8.x4.shared.b16 {%0,%1,%2,%3}, [%4];" \
                 : "=r"((r)[0]), "=r"((r)[1]), "=r"((r)[2]), "=r"((r)[3]) \
                 : "r"(addr))

#define MMA16816(d, a, b0, b1) \
    asm volatile("mma.sync.aligned.m16n8k16.row.col.f32.f16.f16.f32 " \
                 "{%0,%1,%2,%3}, {%4,%5,%6,%7}, {%8,%9}, {%0,%1,%2,%3};" \
                 : "+f"((d)[0]), "+f"((d)[1]), "+f"((d)[2]), "+f"((d)[3]) \
                 : "r"((a)[0]), "r"((a)[1]), "r"((a)[2]), "r"((a)[3]), \
                   "r"(b0), "r"(b1))

// ---------------------------------------------------------------------------
// fp16 mma.sync GEMM: C[M,N] = A[M,K] @ B[N,K]^T + bias
// A row-major [M,K] fp16, B row-major [N,K] fp16 (pre-transposed weights).
// CTA tile 128x128, BK=32, warp tile 64x32 (warps 2x4), fp32 accumulators.
// ---------------------------------------------------------------------------
template<bool HALF_OUT>
__global__ __launch_bounds__(256, 2)
void mma_gemm(const __half* __restrict__ A, const __half* __restrict__ B,
              const float* __restrict__ bias, void* __restrict__ Cout,
              int N, int K)
{
    __shared__ __align__(16) char smem[2 * STAGE_B];   // 40 KB
    const uint32_t sbase = smem_u32(smem);
    const int tid = threadIdx.x;
    const int L = tid & 31;
    const int w = tid >> 5;
    const int wm = w >> 2;          // 0..1  (64-row slabs)
    const int wn = w & 3;           // 0..3  (32-col slabs)
    const int m0 = blockIdx.y * 128;
    const int n0 = blockIdx.x * 128;

    // cp.async plan: thread t copies rows (t>>2) and 64+(t>>2), 16B seg (t&3)
    const int lrow = tid >> 2;
    const int lseg = tid & 3;
    const __half* gA0 = A + (size_t)(m0 + lrow) * K + lseg * 8;
    const __half* gA1 = gA0 + (size_t)64 * K;
    const __half* gB0 = B + (size_t)(n0 + lrow) * K + lseg * 8;
    const __half* gB1 = gB0 + (size_t)64 * K;
    const uint32_t sA0 = (uint32_t)(lrow * ROW_B + lseg * 16);
    const uint32_t sA1 = sA0 + 64 * ROW_B;
    const uint32_t sB0 = ATILE_B + sA0;
    const uint32_t sB1 = ATILE_B + sA1;

    // ldmatrix lane address offsets (bytes within a stage)
    const uint32_t a_off = (uint32_t)(((wm * 64 + (L & 15)) * 40 + (L >> 4) * 8) * 2);
    const uint32_t b_off = (uint32_t)(ATILE_B
        + ((wn * 32 + (L & 7) + ((L >> 4) & 1) * 8) * 40 + ((L >> 3) & 1) * 8) * 2);

    float acc[4][4][4];
    #pragma unroll
    for (int mf = 0; mf < 4; mf++)
        #pragma unroll
        for (int nf = 0; nf < 4; nf++)
            #pragma unroll
            for (int i = 0; i < 4; i++) acc[mf][nf][i] = 0.0f;

    const int NK = K >> 5;   // chunks of 32

    // Prologue: chunk 0 -> stage 0
    {
        cp16(sbase + sA0, gA0); cp16(sbase + sA1, gA1);
        cp16(sbase + sB0, gB0); cp16(sbase + sB1, gB1);
        CP_COMMIT();
    }

    for (int c = 0; c < NK; c++) {
        const int s = c & 1;
        if (c + 1 < NK) {
            const uint32_t st = sbase + (s ^ 1) * STAGE_B;
            const int ko = (c + 1) * 32;
            cp16(st + sA0, gA0 + ko); cp16(st + sA1, gA1 + ko);
            cp16(st + sB0, gB0 + ko); cp16(st + sB1, gB1 + ko);
            CP_COMMIT();
            CP_WAIT(1);
        } else {
            CP_WAIT(0);
        }
        __syncthreads();

        const uint32_t aB = sbase + s * STAGE_B + a_off;
        const uint32_t bB = sbase + s * STAGE_B + b_off;
        #pragma unroll
        for (int ks = 0; ks < 2; ks++) {
            uint32_t a[4][4], b[2][4];
            #pragma unroll
            for (int mf = 0; mf < 4; mf++)
                LDSM_X4(a[mf], aB + mf * (16 * ROW_B) + ks * 32);
            #pragma unroll
            for (int np = 0; np < 2; np++)
                LDSM_X4(b[np], bB + np * (16 * ROW_B) + ks * 32);
            #pragma unroll
            for (int mf = 0; mf < 4; mf++)
                #pragma unroll
                for (int nf = 0; nf < 4; nf++)
                    MMA16816(acc[mf][nf], a[mf],
                             b[nf >> 1][(nf & 1) * 2], b[nf >> 1][(nf & 1) * 2 + 1]);
        }
        __syncthreads();
    }

    // Epilogue: bias + store (half2 or float2)
    const int r0 = m0 + wm * 64 + (L >> 2);
    const int cb = n0 + wn * 32 + (L & 3) * 2;
    #pragma unroll
    for (int nf = 0; nf < 4; nf++) {
        const int col = cb + nf * 8;
        const float bx = __ldg(bias + col);
        const float by = __ldg(bias + col + 1);
        #pragma unroll
        for (int mf = 0; mf < 4; mf++) {
            const int ra = r0 + mf * 16;
            const int rb = ra + 8;
            if (HALF_OUT) {
                __half* C = (__half*)Cout;
                __half2 h0 = __floats2half2_rn(acc[mf][nf][0] + bx, acc[mf][nf][1] + by);
                __half2 h1 = __floats2half2_rn(acc[mf][nf][2] + bx, acc[mf][nf][3] + by);
                *reinterpret_cast<__half2*>(C + (size_t)ra * N + col) = h0;
                *reinterpret_cast<__half2*>(C + (size_t)rb * N + col) = h1;
            } else {
                float* C = (float*)Cout;
                float2 f0 = make_float2(acc[mf][nf][0] + bx, acc[mf][nf][1] + by);
                float2 f1 = make_float2(acc[mf][nf][2] + bx, acc[mf][nf][3] + by);
                *reinterpret_cast<float2*>(C + (size_t)ra * N + col) = f0;
                *reinterpret_cast<float2*>(C + (size_t)rb * N + col) = f1;
            }
        }
    }
}

// ---------------------------------------------------------------------------
// fp32 -> fp16 convert (8 elems/thread, coalesced)
// ---------------------------------------------------------------------------
__global__ __launch_bounds__(256)
void split_kernel(const float* __restrict__ in, __half* __restrict__ out)
{
    const int i = blockIdx.x * 256 + threadIdx.x;
    const float4* in4 = reinterpret_cast<const float4*>(in);
    float4 a = in4[2 * i], b = in4[2 * i + 1];
    float v[8] = {a.x, a.y, a.z, a.w, b.x, b.y, b.z, b.w};
    __half h[8];
    #pragma unroll
    for (int j = 0; j < 8; j++) h[j] = __float2half_rn(v[j]);
    reinterpret_cast<uint4*>(out)[i] = *reinterpret_cast<uint4*>(h);
}

// ---------------------------------------------------------------------------
// W[K,N] fp32 -> transposed fp16 [N,K]
// ---------------------------------------------------------------------------
__global__ __launch_bounds__(256)
void wsplit_kernel(const float* __restrict__ W, __half* __restrict__ T,
                   int K, int N)
{
    __shared__ float t[32][33];
    const int n0 = blockIdx.x * 32, k0 = blockIdx.y * 32;
    const int tx = threadIdx.x & 31, ty = threadIdx.x >> 5;   // 32 x 8
    #pragma unroll
    for (int r = 0; r < 32; r += 8)
        t[ty + r][tx] = W[(size_t)(k0 + ty + r) * N + n0 + tx];
    __syncthreads();
    #pragma unroll
    for (int r = 0; r < 32; r += 8) {
        float v = t[tx][ty + r];
        T[(size_t)(n0 + ty + r) * K + k0 + tx] = __float2half_rn(v);
    }
}

// ---------------------------------------------------------------------------
// Per-token 16x16 cross-head attention, fp16 in -> fp16 out (fp32 compute).
// ---------------------------------------------------------------------------
__global__ __launch_bounds__(128)
void attn_kernel(const __half* __restrict__ qkv, __half* __restrict__ out)
{
    __shared__ float row[N_QKV];
    __shared__ float sc[NHEAD][NHEAD + 1];

    const int t = threadIdx.x;
    const size_t tok = blockIdx.x;
    const uint4* src = reinterpret_cast<const uint4*>(qkv + tok * (size_t)N_QKV);

    // Load 3072 halves -> fp32 smem (8 halves per uint4)
    for (int i = t; i < N_QKV / 8; i += 128) {
        uint4 v = src[i];
        const __half2* h = reinterpret_cast<const __half2*>(&v);
        #pragma unroll
        for (int j = 0; j < 4; j++) {
            float2 f = __half22float2(h[j]);
            row[i * 8 + j * 2 + 0] = f.x;
            row[i * 8 + j * 2 + 1] = f.y;
        }
    }
    __syncthreads();

    #pragma unroll
    for (int p = t; p < NHEAD * NHEAD; p += 128) {
        const int qh = p >> 4, kh = p & 15;
        const float* q  = row + qh * 192;
        const float* kk = row + kh * 192 + 64;
        float s = 0.0f;
        #pragma unroll
        for (int d = 0; d < HDIM; d++) s = fmaf(q[d], kk[d], s);
        sc[qh][kh] = s * 0.125f;   // 1/sqrt(64)
    }
    __syncthreads();

    if (t < NHEAD) {
        float m = sc[t][0];
        #pragma unroll
        for (int j = 1; j < NHEAD; j++) m = fmaxf(m, sc[t][j]);
        float sum = 0.0f;
        #pragma unroll
        for (int j = 0; j < NHEAD; j++) {
            float e = __expf(sc[t][j] - m);
            sc[t][j] = e; sum += e;
        }
        float inv = 1.0f / sum;
        #pragma unroll
        for (int j = 0; j < NHEAD; j++) sc[t][j] *= inv;
    }
    __syncthreads();

    const size_t ob = tok * (size_t)DDIM;
    #pragma unroll
    for (int o = t; o < DDIM; o += 128) {
        const int qh = o >> 6, d = o & 63;
        float a = 0.0f;
        #pragma unroll
        for (int kh = 0; kh < NHEAD; kh++)
            a = fmaf(sc[qh][kh], row[kh * 192 + 128 + d], a);
        out[ob + o] = __float2half_rn(a);
    }
}

// ---------------------------------------------------------------------------
extern "C" void kernel_launch(void* const* d_in, const int* in_sizes, int n_in,
                              void* d_out, int out_size)
{
    (void)in_sizes; (void)n_in; (void)out_size;
    const float* x     = (const float*)d_in[0];
    const float* W_qkv = (const float*)d_in[1];
    const float* b_qkv = (const float*)d_in[2];
    const float* W_out = (const float*)d_in[3];
    const float* b_out = (const float*)d_in[4];
    float* out = (float*)d_out;

    void *p_xh, *p_qkv, *p_ah, *p_wqh, *p_woh;
    cudaGetSymbolAddress(&p_xh,  g_xh);
    cudaGetSymbolAddress(&p_qkv, g_qkv);
    cudaGetSymbolAddress(&p_ah,  g_ah);
    cudaGetSymbolAddress(&p_wqh, g_wqh);
    cudaGetSymbolAddress(&p_woh, g_woh);

    // 1) x -> fp16
    split_kernel<<<(MTOT * DDIM) / 8 / 256, 256>>>(x, (__half*)p_xh);
    // 2) weights -> transposed fp16 [N,K]
    wsplit_kernel<<<dim3(N_QKV / 32, DDIM / 32), 256>>>(
        W_qkv, (__half*)p_wqh, DDIM, N_QKV);
    wsplit_kernel<<<dim3(DDIM / 32, DDIM / 32), 256>>>(
        W_out, (__half*)p_woh, DDIM, DDIM);
    // 3) GEMM1: qkv(fp16) = x @ W_qkv + b_qkv
    mma_gemm<true><<<dim3(N_QKV / 128, MTOT / 128), 256>>>(
        (const __half*)p_xh, (const __half*)p_wqh, b_qkv, p_qkv, N_QKV, DDIM);
    // 4) per-token attention (fp16 -> fp16)
    attn_kernel<<<MTOT, 128>>>((const __half*)p_qkv, (__half*)p_ah);
    // 5) GEMM2: out(fp32) = attn @ W_out + b_out
    mma_gemm<false><<<dim3(DDIM / 128, MTOT / 128), 256>>>(
        (const __half*)p_ah, (const __half*)p_woh, b_out, (void*)out, DDIM, DDIM);
}

// round 11
// speedup vs baseline: 4.6486x; 1.5758x over previous
#include <cuda_runtime.h>
#include <cuda_fp16.h>
#include <math.h>
#include <stdint.h>

// Fixed shapes: B=8, S=4096, D=1024, H=16, hd=64
#define MTOT  32768
#define DDIM  1024
#define N_QKV 3072
#define NHEAD 16
#define HDIM  64

// GEMM tiling: BM=BN=128, BK=32, 8 warps, 4-stage cp.async pipeline
#define ROW_B   80                   // padded smem row: 40 halves = 80 bytes
#define ATILE_B (128 * ROW_B)        // 10240
#define STAGE_B (2 * ATILE_B)        // 20480 (A tile + B tile)
#define STAGES  4
#define SMEM_GEMM (STAGES * STAGE_B) // 81920

// ---------------- scratch (device globals; allocation-free) ----------------
__device__ __align__(16) __half g_xh  [(size_t)MTOT * DDIM];    // 64 MB
__device__ __align__(16) __half g_qkv [(size_t)MTOT * N_QKV];   // 192 MB
__device__ __align__(16) __half g_ah  [(size_t)MTOT * DDIM];    // 64 MB
__device__ __align__(16) __half g_wqh [(size_t)N_QKV * DDIM];   // [N,K] 6 MB
__device__ __align__(16) __half g_woh [(size_t)DDIM * DDIM];    // [N,K] 2 MB

// ---------------- PTX helpers (sm_80-level only; no 'a' features) ----------
__device__ __forceinline__ uint32_t smem_u32(const void* p) {
    uint32_t a;
    asm("{ .reg .u64 t; cvta.to.shared.u64 t, %1; cvt.u32.u64 %0, t; }"
        : "=r"(a) : "l"(p));
    return a;
}
__device__ __forceinline__ void cp16(uint32_t dst, const void* src) {
    asm volatile("cp.async.cg.shared.global [%0], [%1], 16;"
                 :: "r"(dst), "l"(src) : "memory");
}
#define CP_COMMIT() asm volatile("cp.async.commit_group;" ::: "memory")
#define CP_WAIT(n)  asm volatile("cp.async.wait_group %0;" :: "n"(n) : "memory")

#define LDSM_X4(r, addr) \
    asm volatile("ldmatrix.sync.aligned.m8n8.x4.shared.b16 {%0,%1,%2,%3}, [%4];" \
                 : "=r"((r)[0]), "=r"((r)[1]), "=r"((r)[2]), "=r"((r)[3]) \
                 : "r"(addr))

#define MMA16816(d, a, b0, b1) \
    asm volatile("mma.sync.aligned.m16n8k16.row.col.f32.f16.f16.f32 " \
                 "{%0,%1,%2,%3}, {%4,%5,%6,%7}, {%8,%9}, {%0,%1,%2,%3};" \
                 : "+f"((d)[0]), "+f"((d)[1]), "+f"((d)[2]), "+f"((d)[3]) \
                 : "r"((a)[0]), "r"((a)[1]), "r"((a)[2]), "r"((a)[3]), \
                   "r"(b0), "r"(b1))

// ---------------------------------------------------------------------------
// fp16 mma.sync GEMM: C[M,N] = A[M,K] @ B[N,K]^T + bias
// A row-major [M,K] fp16, B row-major [N,K] fp16 (pre-transposed weights).
// CTA tile 128x128, BK=32, warp tile 64x32 (warps 2x4), fp32 accumulators.
// 4-stage cp.async pipeline, ONE __syncthreads per K-chunk.
// ---------------------------------------------------------------------------
template<bool HALF_OUT>
__global__ __launch_bounds__(256, 2)
void mma_gemm(const __half* __restrict__ A, const __half* __restrict__ B,
              const float* __restrict__ bias, void* __restrict__ Cout,
              int N, int K)
{
    extern __shared__ __align__(16) char smem[];
    const uint32_t sbase = smem_u32(smem);
    const int tid = threadIdx.x;
    const int L = tid & 31;
    const int w = tid >> 5;
    const int wm = w >> 2;          // 0..1  (64-row slabs)
    const int wn = w & 3;           // 0..3  (32-col slabs)
    const int m0 = blockIdx.y * 128;
    const int n0 = blockIdx.x * 128;

    // cp.async plan: thread t copies rows (t>>2) and 64+(t>>2), 16B seg (t&3)
    const int lrow = tid >> 2;
    const int lseg = tid & 3;
    const __half* gA0 = A + (size_t)(m0 + lrow) * K + lseg * 8;
    const __half* gA1 = gA0 + (size_t)64 * K;
    const __half* gB0 = B + (size_t)(n0 + lrow) * K + lseg * 8;
    const __half* gB1 = gB0 + (size_t)64 * K;
    const uint32_t sA0 = (uint32_t)(lrow * ROW_B + lseg * 16);
    const uint32_t sA1 = sA0 + 64 * ROW_B;
    const uint32_t sB0 = ATILE_B + sA0;
    const uint32_t sB1 = ATILE_B + sA1;

    // ldmatrix lane address offsets (bytes within a stage)
    const uint32_t a_off = (uint32_t)(((wm * 64 + (L & 15)) * 40 + (L >> 4) * 8) * 2);
    const uint32_t b_off = (uint32_t)(ATILE_B
        + ((wn * 32 + (L & 7) + ((L >> 4) & 1) * 8) * 40 + ((L >> 3) & 1) * 8) * 2);

    float acc[4][4][4];
    #pragma unroll
    for (int mf = 0; mf < 4; mf++)
        #pragma unroll
        for (int nf = 0; nf < 4; nf++)
            #pragma unroll
            for (int i = 0; i < 4; i++) acc[mf][nf][i] = 0.0f;

    const int NK = K >> 5;   // chunks of 32 (= 32 for K=1024)

    // Prologue: stages 0..2 in flight
    #pragma unroll
    for (int s = 0; s < STAGES - 1; s++) {
        const uint32_t st = sbase + s * STAGE_B;
        const int ko = s * 32;
        cp16(st + sA0, gA0 + ko); cp16(st + sA1, gA1 + ko);
        cp16(st + sB0, gB0 + ko); cp16(st + sB1, gB1 + ko);
        CP_COMMIT();
    }

    for (int c = 0; c < NK; c++) {
        // Ensure stage c resident (tail iterations need tighter bounds)
        if (c < NK - 2)      CP_WAIT(2);
        else if (c == NK - 2) CP_WAIT(1);
        else                  CP_WAIT(0);
        __syncthreads();   // all warps done computing stage c-1 -> its buffer is free

        // Prefetch stage c+3 into buffer (c+3)%4 == (c-1)%4 (just freed)
        if (c + STAGES - 1 < NK) {
            const uint32_t st = sbase + ((c + STAGES - 1) & (STAGES - 1)) * STAGE_B;
            const int ko = (c + STAGES - 1) * 32;
            cp16(st + sA0, gA0 + ko); cp16(st + sA1, gA1 + ko);
            cp16(st + sB0, gB0 + ko); cp16(st + sB1, gB1 + ko);
            CP_COMMIT();
        }

        // Compute stage c
        const uint32_t aB = sbase + (c & (STAGES - 1)) * STAGE_B + a_off;
        const uint32_t bB = sbase + (c & (STAGES - 1)) * STAGE_B + b_off;
        #pragma unroll
        for (int ks = 0; ks < 2; ks++) {
            uint32_t a[4][4], b[2][4];
            #pragma unroll
            for (int mf = 0; mf < 4; mf++)
                LDSM_X4(a[mf], aB + mf * (16 * ROW_B) + ks * 32);
            #pragma unroll
            for (int np = 0; np < 2; np++)
                LDSM_X4(b[np], bB + np * (16 * ROW_B) + ks * 32);
            #pragma unroll
            for (int mf = 0; mf < 4; mf++)
                #pragma unroll
                for (int nf = 0; nf < 4; nf++)
                    MMA16816(acc[mf][nf], a[mf],
                             b[nf >> 1][(nf & 1) * 2], b[nf >> 1][(nf & 1) * 2 + 1]);
        }
    }

    // Epilogue: bias + store (half2 or float2)
    const int r0 = m0 + wm * 64 + (L >> 2);
    const int cb = n0 + wn * 32 + (L & 3) * 2;
    #pragma unroll
    for (int nf = 0; nf < 4; nf++) {
        const int col = cb + nf * 8;
        const float bx = __ldg(bias + col);
        const float by = __ldg(bias + col + 1);
        #pragma unroll
        for (int mf = 0; mf < 4; mf++) {
            const int ra = r0 + mf * 16;
            const int rb = ra + 8;
            if (HALF_OUT) {
                __half* C = (__half*)Cout;
                __half2 h0 = __floats2half2_rn(acc[mf][nf][0] + bx, acc[mf][nf][1] + by);
                __half2 h1 = __floats2half2_rn(acc[mf][nf][2] + bx, acc[mf][nf][3] + by);
                *reinterpret_cast<__half2*>(C + (size_t)ra * N + col) = h0;
                *reinterpret_cast<__half2*>(C + (size_t)rb * N + col) = h1;
            } else {
                float* C = (float*)Cout;
                float2 f0 = make_float2(acc[mf][nf][0] + bx, acc[mf][nf][1] + by);
                float2 f1 = make_float2(acc[mf][nf][2] + bx, acc[mf][nf][3] + by);
                *reinterpret_cast<float2*>(C + (size_t)ra * N + col) = f0;
                *reinterpret_cast<float2*>(C + (size_t)rb * N + col) = f1;
            }
        }
    }
}

// ---------------------------------------------------------------------------
// fp32 -> fp16 convert (8 elems/thread, coalesced)
// ---------------------------------------------------------------------------
__global__ __launch_bounds__(256)
void split_kernel(const float* __restrict__ in, __half* __restrict__ out)
{
    const int i = blockIdx.x * 256 + threadIdx.x;
    const float4* in4 = reinterpret_cast<const float4*>(in);
    float4 a = in4[2 * i], b = in4[2 * i + 1];
    float v[8] = {a.x, a.y, a.z, a.w, b.x, b.y, b.z, b.w};
    __half h[8];
    #pragma unroll
    for (int j = 0; j < 8; j++) h[j] = __float2half_rn(v[j]);
    reinterpret_cast<uint4*>(out)[i] = *reinterpret_cast<uint4*>(h);
}

// ---------------------------------------------------------------------------
// W[K,N] fp32 -> transposed fp16 [N,K]
// ---------------------------------------------------------------------------
__global__ __launch_bounds__(256)
void wsplit_kernel(const float* __restrict__ W, __half* __restrict__ T,
                   int K, int N)
{
    __shared__ float t[32][33];
    const int n0 = blockIdx.x * 32, k0 = blockIdx.y * 32;
    const int tx = threadIdx.x & 31, ty = threadIdx.x >> 5;   // 32 x 8
    #pragma unroll
    for (int r = 0; r < 32; r += 8)
        t[ty + r][tx] = W[(size_t)(k0 + ty + r) * N + n0 + tx];
    __syncthreads();
    #pragma unroll
    for (int r = 0; r < 32; r += 8) {
        float v = t[tx][ty + r];
        T[(size_t)(n0 + ty + r) * K + k0 + tx] = __float2half_rn(v);
    }
}

// ---------------------------------------------------------------------------
// Per-token 16x16 cross-head attention, fp16 in -> fp16 out (fp32 compute).
// ---------------------------------------------------------------------------
__global__ __launch_bounds__(128)
void attn_kernel(const __half* __restrict__ qkv, __half* __restrict__ out)
{
    __shared__ float row[N_QKV];
    __shared__ float sc[NHEAD][NHEAD + 1];

    const int t = threadIdx.x;
    const size_t tok = blockIdx.x;
    const uint4* src = reinterpret_cast<const uint4*>(qkv + tok * (size_t)N_QKV);

    // Load 3072 halves -> fp32 smem (8 halves per uint4)
    for (int i = t; i < N_QKV / 8; i += 128) {
        uint4 v = src[i];
        const __half2* h = reinterpret_cast<const __half2*>(&v);
        #pragma unroll
        for (int j = 0; j < 4; j++) {
            float2 f = __half22float2(h[j]);
            row[i * 8 + j * 2 + 0] = f.x;
            row[i * 8 + j * 2 + 1] = f.y;
        }
    }
    __syncthreads();

    #pragma unroll
    for (int p = t; p < NHEAD * NHEAD; p += 128) {
        const int qh = p >> 4, kh = p & 15;
        const float* q  = row + qh * 192;
        const float* kk = row + kh * 192 + 64;
        float s = 0.0f;
        #pragma unroll
        for (int d = 0; d < HDIM; d++) s = fmaf(q[d], kk[d], s);
        sc[qh][kh] = s * 0.125f;   // 1/sqrt(64)
    }
    __syncthreads();

    if (t < NHEAD) {
        float m = sc[t][0];
        #pragma unroll
        for (int j = 1; j < NHEAD; j++) m = fmaxf(m, sc[t][j]);
        float sum = 0.0f;
        #pragma unroll
        for (int j = 0; j < NHEAD; j++) {
            float e = __expf(sc[t][j] - m);
            sc[t][j] = e; sum += e;
        }
        float inv = 1.0f / sum;
        #pragma unroll
        for (int j = 0; j < NHEAD; j++) sc[t][j] *= inv;
    }
    __syncthreads();

    const size_t ob = tok * (size_t)DDIM;
    #pragma unroll
    for (int o = t; o < DDIM; o += 128) {
        const int qh = o >> 6, d = o & 63;
        float a = 0.0f;
        #pragma unroll
        for (int kh = 0; kh < NHEAD; kh++)
            a = fmaf(sc[qh][kh], row[kh * 192 + 128 + d], a);
        out[ob + o] = __float2half_rn(a);
    }
}

// ---------------------------------------------------------------------------
extern "C" void kernel_launch(void* const* d_in, const int* in_sizes, int n_in,
                              void* d_out, int out_size)
{
    (void)in_sizes; (void)n_in; (void)out_size;
    const float* x     = (const float*)d_in[0];
    const float* W_qkv = (const float*)d_in[1];
    const float* b_qkv = (const float*)d_in[2];
    const float* W_out = (const float*)d_in[3];
    const float* b_out = (const float*)d_in[4];
    float* out = (float*)d_out;

    void *p_xh, *p_qkv, *p_ah, *p_wqh, *p_woh;
    cudaGetSymbolAddress(&p_xh,  g_xh);
    cudaGetSymbolAddress(&p_qkv, g_qkv);
    cudaGetSymbolAddress(&p_ah,  g_ah);
    cudaGetSymbolAddress(&p_wqh, g_wqh);
    cudaGetSymbolAddress(&p_woh, g_woh);

    cudaFuncSetAttribute(mma_gemm<true>,
                         cudaFuncAttributeMaxDynamicSharedMemorySize, SMEM_GEMM);
    cudaFuncSetAttribute(mma_gemm<false>,
                         cudaFuncAttributeMaxDynamicSharedMemorySize, SMEM_GEMM);

    // 1) x -> fp16
    split_kernel<<<(MTOT * DDIM) / 8 / 256, 256>>>(x, (__half*)p_xh);
    // 2) weights -> transposed fp16 [N,K]
    wsplit_kernel<<<dim3(N_QKV / 32, DDIM / 32), 256>>>(
        W_qkv, (__half*)p_wqh, DDIM, N_QKV);
    wsplit_kernel<<<dim3(DDIM / 32, DDIM / 32), 256>>>(
        W_out, (__half*)p_woh, DDIM, DDIM);
    // 3) GEMM1: qkv(fp16) = x @ W_qkv + b_qkv
    mma_gemm<true><<<dim3(N_QKV / 128, MTOT / 128), 256, SMEM_GEMM>>>(
        (const __half*)p_xh, (const __half*)p_wqh, b_qkv, p_qkv, N_QKV, DDIM);
    // 4) per-token attention (fp16 -> fp16)
    attn_kernel<<<MTOT, 128>>>((const __half*)p_qkv, (__half*)p_ah);
    // 5) GEMM2: out(fp32) = attn @ W_out + b_out
    mma_gemm<false><<<dim3(DDIM / 128, MTOT / 128), 256, SMEM_GEMM>>>(
        (const __half*)p_ah, (const __half*)p_woh, b_out, (void*)out, DDIM, DDIM);
}

// round 12
// speedup vs baseline: 5.3295x; 1.1465x over previous
#include <cuda_runtime.h>
#include <cuda_fp16.h>
#include <math.h>
#include <stdint.h>

// Fixed shapes: B=8, S=4096, D=1024, H=16, hd=64
#define MTOT  32768
#define DDIM  1024
#define N_QKV 3072
#define NHEAD 16
#define HDIM  64

// GEMM tiling: BM=BN=128, BK=32, 4 warps (warp tile 64x64), 4-stage cp.async
#define ROW_B   80                   // padded smem row: 40 halves = 80 bytes
#define ATILE_B (128 * ROW_B)        // 10240
#define STAGE_B (2 * ATILE_B)        // 20480 (A tile + B tile)
#define STAGES  4
#define SMEM_GEMM (STAGES * STAGE_B) // 81920

// ---------------- scratch (device globals; allocation-free) ----------------
__device__ __align__(16) __half g_xh  [(size_t)MTOT * DDIM];    // 64 MB
__device__ __align__(16) __half g_qkv [(size_t)MTOT * N_QKV];   // 192 MB
__device__ __align__(16) __half g_ah  [(size_t)MTOT * DDIM];    // 64 MB
__device__ __align__(16) __half g_wqh [(size_t)N_QKV * DDIM];   // [N,K] 6 MB
__device__ __align__(16) __half g_woh [(size_t)DDIM * DDIM];    // [N,K] 2 MB

// ---------------- PTX helpers (sm_80-level only; no 'a' features) ----------
__device__ __forceinline__ uint32_t smem_u32(const void* p) {
    uint32_t a;
    asm("{ .reg .u64 t; cvta.to.shared.u64 t, %1; cvt.u32.u64 %0, t; }"
        : "=r"(a) : "l"(p));
    return a;
}
__device__ __forceinline__ void cp16(uint32_t dst, const void* src) {
    asm volatile("cp.async.cg.shared.global [%0], [%1], 16;"
                 :: "r"(dst), "l"(src) : "memory");
}
#define CP_COMMIT() asm volatile("cp.async.commit_group;" ::: "memory")
#define CP_WAIT(n)  asm volatile("cp.async.wait_group %0;" :: "n"(n) : "memory")

#define LDSM_X4(r, addr) \
    asm volatile("ldmatrix.sync.aligned.m8n8.x4.shared.b16 {%0,%1,%2,%3}, [%4];" \
                 : "=r"((r)[0]), "=r"((r)[1]), "=r"((r)[2]), "=r"((r)[3]) \
                 : "r"(addr))

#define MMA16816(d, a, b0, b1) \
    asm volatile("mma.sync.aligned.m16n8k16.row.col.f32.f16.f16.f32 " \
                 "{%0,%1,%2,%3}, {%4,%5,%6,%7}, {%8,%9}, {%0,%1,%2,%3};" \
                 : "+f"((d)[0]), "+f"((d)[1]), "+f"((d)[2]), "+f"((d)[3]) \
                 : "r"((a)[0]), "r"((a)[1]), "r"((a)[2]), "r"((a)[3]), \
                   "r"(b0), "r"(b1))

// ---------------------------------------------------------------------------
// fp16 mma.sync GEMM: C[M,N] = A[M,K] @ B[N,K]^T + bias
// A row-major [M,K] fp16, B row-major [N,K] fp16 (pre-transposed weights).
// CTA tile 128x128, BK=32, 4 warps each 64x64, fp32 accumulators.
// 4-stage cp.async pipeline, ONE __syncthreads per K-chunk, 2 CTAs/SM.
// ---------------------------------------------------------------------------
template<bool HALF_OUT>
__global__ __launch_bounds__(128, 2)
void mma_gemm(const __half* __restrict__ A, const __half* __restrict__ B,
              const float* __restrict__ bias, void* __restrict__ Cout,
              int N, int K)
{
    extern __shared__ __align__(16) char smem[];
    const uint32_t sbase = smem_u32(smem);
    const int tid = threadIdx.x;
    const int L = tid & 31;
    const int w = tid >> 5;
    const int wm = w >> 1;          // 0..1  (64-row slabs)
    const int wn = w & 1;           // 0..1  (64-col slabs)
    const int m0 = blockIdx.y * 128;
    const int n0 = blockIdx.x * 128;

    // cp.async plan: 128 threads x 8 segments: rows (tid>>2)+32*i, 16B seg (tid&3)
    const int lrow = tid >> 2;      // 0..31
    const int lseg = tid & 3;
    const __half* gA[4];
    const __half* gB[4];
    uint32_t sA[4], sB[4];
    #pragma unroll
    for (int i = 0; i < 4; i++) {
        const int r = lrow + 32 * i;
        gA[i] = A + (size_t)(m0 + r) * K + lseg * 8;
        gB[i] = B + (size_t)(n0 + r) * K + lseg * 8;
        sA[i] = (uint32_t)(r * ROW_B + lseg * 16);
        sB[i] = ATILE_B + sA[i];
    }

    // ldmatrix lane address offsets (bytes within a stage)
    const uint32_t a_off = (uint32_t)(((wm * 64 + (L & 15)) * 40 + (L >> 4) * 8) * 2);
    const uint32_t b_off = (uint32_t)(ATILE_B
        + ((wn * 64 + (L & 7) + ((L >> 4) & 1) * 8) * 40 + ((L >> 3) & 1) * 8) * 2);

    float acc[4][8][4];
    #pragma unroll
    for (int mf = 0; mf < 4; mf++)
        #pragma unroll
        for (int nf = 0; nf < 8; nf++)
            #pragma unroll
            for (int i = 0; i < 4; i++) acc[mf][nf][i] = 0.0f;

    const int NK = K >> 5;   // chunks of 32 (= 32 for K=1024)

    // Prologue: stages 0..2 in flight
    #pragma unroll
    for (int s = 0; s < STAGES - 1; s++) {
        const uint32_t st = sbase + s * STAGE_B;
        const int ko = s * 32;
        #pragma unroll
        for (int i = 0; i < 4; i++) {
            cp16(st + sA[i], gA[i] + ko);
            cp16(st + sB[i], gB[i] + ko);
        }
        CP_COMMIT();
    }

    for (int c = 0; c < NK; c++) {
        if (c < NK - 2)       CP_WAIT(2);
        else if (c == NK - 2) CP_WAIT(1);
        else                  CP_WAIT(0);
        __syncthreads();   // stage c-1 consumed by all warps -> buffer free

        // Prefetch stage c+3 into buffer (c+3)%4
        if (c + STAGES - 1 < NK) {
            const uint32_t st = sbase + ((c + STAGES - 1) & (STAGES - 1)) * STAGE_B;
            const int ko = (c + STAGES - 1) * 32;
            #pragma unroll
            for (int i = 0; i < 4; i++) {
                cp16(st + sA[i], gA[i] + ko);
                cp16(st + sB[i], gB[i] + ko);
            }
            CP_COMMIT();
        }

        // Compute stage c: 2 ks-steps x (8 LDSM + 32 HMMA)
        const uint32_t aB = sbase + (c & (STAGES - 1)) * STAGE_B + a_off;
        const uint32_t bB = sbase + (c & (STAGES - 1)) * STAGE_B + b_off;
        #pragma unroll
        for (int ks = 0; ks < 2; ks++) {
            uint32_t a[4][4], b[4][4];
            #pragma unroll
            for (int mf = 0; mf < 4; mf++)
                LDSM_X4(a[mf], aB + mf * (16 * ROW_B) + ks * 32);
            #pragma unroll
            for (int np = 0; np < 4; np++)
                LDSM_X4(b[np], bB + np * (16 * ROW_B) + ks * 32);
            #pragma unroll
            for (int mf = 0; mf < 4; mf++)
                #pragma unroll
                for (int nf = 0; nf < 8; nf++)
                    MMA16816(acc[mf][nf], a[mf],
                             b[nf >> 1][(nf & 1) * 2], b[nf >> 1][(nf & 1) * 2 + 1]);
        }
    }

    // Epilogue: bias + store (half2 or float2)
    const int r0 = m0 + wm * 64 + (L >> 2);
    const int cb = n0 + wn * 64 + (L & 3) * 2;
    #pragma unroll
    for (int nf = 0; nf < 8; nf++) {
        const int col = cb + nf * 8;
        const float bx = __ldg(bias + col);
        const float by = __ldg(bias + col + 1);
        #pragma unroll
        for (int mf = 0; mf < 4; mf++) {
            const int ra = r0 + mf * 16;
            const int rb = ra + 8;
            if (HALF_OUT) {
                __half* C = (__half*)Cout;
                __half2 h0 = __floats2half2_rn(acc[mf][nf][0] + bx, acc[mf][nf][1] + by);
                __half2 h1 = __floats2half2_rn(acc[mf][nf][2] + bx, acc[mf][nf][3] + by);
                *reinterpret_cast<__half2*>(C + (size_t)ra * N + col) = h0;
                *reinterpret_cast<__half2*>(C + (size_t)rb * N + col) = h1;
            } else {
                float* C = (float*)Cout;
                float2 f0 = make_float2(acc[mf][nf][0] + bx, acc[mf][nf][1] + by);
                float2 f1 = make_float2(acc[mf][nf][2] + bx, acc[mf][nf][3] + by);
                *reinterpret_cast<float2*>(C + (size_t)ra * N + col) = f0;
                *reinterpret_cast<float2*>(C + (size_t)rb * N + col) = f1;
            }
        }
    }
}

// ---------------------------------------------------------------------------
// fp32 -> fp16 convert (8 elems/thread, coalesced)
// ---------------------------------------------------------------------------
__global__ __launch_bounds__(256)
void split_kernel(const float* __restrict__ in, __half* __restrict__ out)
{
    const int i = blockIdx.x * 256 + threadIdx.x;
    const float4* in4 = reinterpret_cast<const float4*>(in);
    float4 a = in4[2 * i], b = in4[2 * i + 1];
    float v[8] = {a.x, a.y, a.z, a.w, b.x, b.y, b.z, b.w};
    __half h[8];
    #pragma unroll
    for (int j = 0; j < 8; j++) h[j] = __float2half_rn(v[j]);
    reinterpret_cast<uint4*>(out)[i] = *reinterpret_cast<uint4*>(h);
}

// ---------------------------------------------------------------------------
// W[K,N] fp32 -> transposed fp16 [N,K]
// ---------------------------------------------------------------------------
__global__ __launch_bounds__(256)
void wsplit_kernel(const float* __restrict__ W, __half* __restrict__ T,
                   int K, int N)
{
    __shared__ float t[32][33];
    const int n0 = blockIdx.x * 32, k0 = blockIdx.y * 32;
    const int tx = threadIdx.x & 31, ty = threadIdx.x >> 5;   // 32 x 8
    #pragma unroll
    for (int r = 0; r < 32; r += 8)
        t[ty + r][tx] = W[(size_t)(k0 + ty + r) * N + n0 + tx];
    __syncthreads();
    #pragma unroll
    for (int r = 0; r < 32; r += 8) {
        float v = t[tx][ty + r];
        T[(size_t)(n0 + ty + r) * K + k0 + tx] = __float2half_rn(v);
    }
}

// ---------------------------------------------------------------------------
// Per-token 16x16 cross-head attention, fp16 in -> fp16 out (fp32 compute).
// ---------------------------------------------------------------------------
__global__ __launch_bounds__(128)
void attn_kernel(const __half* __restrict__ qkv, __half* __restrict__ out)
{
    __shared__ float row[N_QKV];
    __shared__ float sc[NHEAD][NHEAD + 1];

    const int t = threadIdx.x;
    const size_t tok = blockIdx.x;
    const uint4* src = reinterpret_cast<const uint4*>(qkv + tok * (size_t)N_QKV);

    // Load 3072 halves -> fp32 smem (8 halves per uint4)
    for (int i = t; i < N_QKV / 8; i += 128) {
        uint4 v = src[i];
        const __half2* h = reinterpret_cast<const __half2*>(&v);
        #pragma unroll
        for (int j = 0; j < 4; j++) {
            float2 f = __half22float2(h[j]);
            row[i * 8 + j * 2 + 0] = f.x;
            row[i * 8 + j * 2 + 1] = f.y;
        }
    }
    __syncthreads();

    #pragma unroll
    for (int p = t; p < NHEAD * NHEAD; p += 128) {
        const int qh = p >> 4, kh = p & 15;
        const float* q  = row + qh * 192;
        const float* kk = row + kh * 192 + 64;
        float s = 0.0f;
        #pragma unroll
        for (int d = 0; d < HDIM; d++) s = fmaf(q[d], kk[d], s);
        sc[qh][kh] = s * 0.125f;   // 1/sqrt(64)
    }
    __syncthreads();

    if (t < NHEAD) {
        float m = sc[t][0];
        #pragma unroll
        for (int j = 1; j < NHEAD; j++) m = fmaxf(m, sc[t][j]);
        float sum = 0.0f;
        #pragma unroll
        for (int j = 0; j < NHEAD; j++) {
            float e = __expf(sc[t][j] - m);
            sc[t][j] = e; sum += e;
        }
        float inv = 1.0f / sum;
        #pragma unroll
        for (int j = 0; j < NHEAD; j++) sc[t][j] *= inv;
    }
    __syncthreads();

    const size_t ob = tok * (size_t)DDIM;
    #pragma unroll
    for (int o = t; o < DDIM; o += 128) {
        const int qh = o >> 6, d = o & 63;
        float a = 0.0f;
        #pragma unroll
        for (int kh = 0; kh < NHEAD; kh++)
            a = fmaf(sc[qh][kh], row[kh * 192 + 128 + d], a);
        out[ob + o] = __float2half_rn(a);
    }
}

// ---------------------------------------------------------------------------
extern "C" void kernel_launch(void* const* d_in, const int* in_sizes, int n_in,
                              void* d_out, int out_size)
{
    (void)in_sizes; (void)n_in; (void)out_size;
    const float* x     = (const float*)d_in[0];
    const float* W_qkv = (const float*)d_in[1];
    const float* b_qkv = (const float*)d_in[2];
    const float* W_out = (const float*)d_in[3];
    const float* b_out = (const float*)d_in[4];
    float* out = (float*)d_out;

    void *p_xh, *p_qkv, *p_ah, *p_wqh, *p_woh;
    cudaGetSymbolAddress(&p_xh,  g_xh);
    cudaGetSymbolAddress(&p_qkv, g_qkv);
    cudaGetSymbolAddress(&p_ah,  g_ah);
    cudaGetSymbolAddress(&p_wqh, g_wqh);
    cudaGetSymbolAddress(&p_woh, g_woh);

    cudaFuncSetAttribute(mma_gemm<true>,
                         cudaFuncAttributeMaxDynamicSharedMemorySize, SMEM_GEMM);
    cudaFuncSetAttribute(mma_gemm<false>,
                         cudaFuncAttributeMaxDynamicSharedMemorySize, SMEM_GEMM);

    // 1) x -> fp16
    split_kernel<<<(MTOT * DDIM) / 8 / 256, 256>>>(x, (__half*)p_xh);
    // 2) weights -> transposed fp16 [N,K]
    wsplit_kernel<<<dim3(N_QKV / 32, DDIM / 32), 256>>>(
        W_qkv, (__half*)p_wqh, DDIM, N_QKV);
    wsplit_kernel<<<dim3(DDIM / 32, DDIM / 32), 256>>>(
        W_out, (__half*)p_woh, DDIM, DDIM);
    // 3) GEMM1: qkv(fp16) = x @ W_qkv + b_qkv
    mma_gemm<true><<<dim3(N_QKV / 128, MTOT / 128), 128, SMEM_GEMM>>>(
        (const __half*)p_xh, (const __half*)p_wqh, b_qkv, p_qkv, N_QKV, DDIM);
    // 4) per-token attention (fp16 -> fp16)
    attn_kernel<<<MTOT, 128>>>((const __half*)p_qkv, (__half*)p_ah);
    // 5) GEMM2: out(fp32) = attn @ W_out + b_out
    mma_gemm<false><<<dim3(DDIM / 128, MTOT / 128), 128, SMEM_GEMM>>>(
        (const __half*)p_ah, (const __half*)p_woh, b_out, (void*)out, DDIM, DDIM);
}

// round 16
// speedup vs baseline: 5.3504x; 1.0039x over previous
#include <cuda_runtime.h>
#include <cuda_fp16.h>
#include <math.h>
#include <stdint.h>

// Fixed shapes: B=8, S=4096, D=1024, H=16, hd=64
#define MTOT  32768
#define DDIM  1024
#define N_QKV 3072
#define NHEAD 16
#define HDIM  64

// GEMM tiling: BM=BN=128, BK=32, 4 warps (warp tile 64x64), 4-stage cp.async
#define ROW_B   80                   // padded smem row: 40 halves = 80 bytes
#define ATILE_B (128 * ROW_B)        // 10240
#define STAGE_B (2 * ATILE_B)        // 20480 (A tile + B tile)
#define STAGES  4
#define SMEM_GEMM (STAGES * STAGE_B) // 81920

// ---------------- scratch (device globals; allocation-free) ----------------
__device__ __align__(16) __half g_xh  [(size_t)MTOT * DDIM];    // 64 MB
__device__ __align__(16) __half g_qkv [(size_t)MTOT * N_QKV];   // 192 MB
__device__ __align__(16) __half g_ah  [(size_t)MTOT * DDIM];    // 64 MB
__device__ __align__(16) __half g_wqh [(size_t)N_QKV * DDIM];   // [N,K] 6 MB
__device__ __align__(16) __half g_woh [(size_t)DDIM * DDIM];    // [N,K] 2 MB

// ---------------- PTX helpers (sm_80-level only; no 'a' features) ----------
__device__ __forceinline__ uint32_t smem_u32(const void* p) {
    uint32_t a;
    asm("{ .reg .u64 t; cvta.to.shared.u64 t, %1; cvt.u32.u64 %0, t; }"
        : "=r"(a) : "l"(p));
    return a;
}
__device__ __forceinline__ void cp16(uint32_t dst, const void* src) {
    asm volatile("cp.async.cg.shared.global [%0], [%1], 16;"
                 :: "r"(dst), "l"(src) : "memory");
}
#define CP_COMMIT() asm volatile("cp.async.commit_group;" ::: "memory")
#define CP_WAIT(n)  asm volatile("cp.async.wait_group %0;" :: "n"(n) : "memory")

#define LDSM_X4(r, addr) \
    asm volatile("ldmatrix.sync.aligned.m8n8.x4.shared.b16 {%0,%1,%2,%3}, [%4];" \
                 : "=r"((r)[0]), "=r"((r)[1]), "=r"((r)[2]), "=r"((r)[3]) \
                 : "r"(addr))

#define MMA16816(d, a, b0, b1) \
    asm volatile("mma.sync.aligned.m16n8k16.row.col.f32.f16.f16.f32 " \
                 "{%0,%1,%2,%3}, {%4,%5,%6,%7}, {%8,%9}, {%0,%1,%2,%3};" \
                 : "+f"((d)[0]), "+f"((d)[1]), "+f"((d)[2]), "+f"((d)[3]) \
                 : "r"((a)[0]), "r"((a)[1]), "r"((a)[2]), "r"((a)[3]), \
                   "r"(b0), "r"(b1))

// ---------------------------------------------------------------------------
// fp16 mma.sync GEMM: C[M,N] = A[M,K] @ B[N,K]^T + bias
// A row-major [M,K] fp16, B row-major [N,K] fp16 (pre-transposed weights).
// CTA tile 128x128, BK=32, 4 warps each 64x64, fp32 accumulators.
// 4-stage cp.async smem pipeline + register-level fragment double buffering:
// LDSMs for step s+1 are issued before the MMAs of step s, so every LDSM
// batch is covered by 32 independent HMMAs.
// ---------------------------------------------------------------------------
template<bool HALF_OUT>
__global__ __launch_bounds__(128, 2)
void mma_gemm(const __half* __restrict__ A, const __half* __restrict__ B,
              const float* __restrict__ bias, void* __restrict__ Cout,
              int N, int K)
{
    extern __shared__ __align__(16) char smem[];
    const uint32_t sbase = smem_u32(smem);
    const int tid = threadIdx.x;
    const int L = tid & 31;
    const int w = tid >> 5;
    const int wm = w >> 1;          // 0..1  (64-row slabs)
    const int wn = w & 1;           // 0..1  (64-col slabs)
    const int m0 = blockIdx.y * 128;
    const int n0 = blockIdx.x * 128;

    // cp.async plan: 128 threads x 8 segments: rows (tid>>2)+32*i, 16B seg (tid&3)
    const int lrow = tid >> 2;      // 0..31
    const int lseg = tid & 3;
    const __half* gA[4];
    const __half* gB[4];
    uint32_t sA[4], sB[4];
    #pragma unroll
    for (int i = 0; i < 4; i++) {
        const int r = lrow + 32 * i;
        gA[i] = A + (size_t)(m0 + r) * K + lseg * 8;
        gB[i] = B + (size_t)(n0 + r) * K + lseg * 8;
        sA[i] = (uint32_t)(r * ROW_B + lseg * 16);
        sB[i] = ATILE_B + sA[i];
    }

    // ldmatrix lane address offsets (bytes within a stage)
    const uint32_t a_off = (uint32_t)(((wm * 64 + (L & 15)) * 40 + (L >> 4) * 8) * 2);
    const uint32_t b_off = (uint32_t)(ATILE_B
        + ((wn * 64 + (L & 7) + ((L >> 4) & 1) * 8) * 40 + ((L >> 3) & 1) * 8) * 2);

    float acc[4][8][4];
    #pragma unroll
    for (int mf = 0; mf < 4; mf++)
        #pragma unroll
        for (int nf = 0; nf < 8; nf++)
            #pragma unroll
            for (int i = 0; i < 4; i++) acc[mf][nf][i] = 0.0f;

    const int NK = K >> 5;   // chunks of 32 (= 32 for K=1024)

    // Double-buffered fragments: fr[0] holds ks0, fr[1] holds ks1
    uint32_t fa[2][4][4], fb[2][4][4];

    // Prologue: stages 0..2 in flight
    #pragma unroll
    for (int s = 0; s < STAGES - 1; s++) {
        const uint32_t st = sbase + s * STAGE_B;
        const int ko = s * 32;
        #pragma unroll
        for (int i = 0; i < 4; i++) {
            cp16(st + sA[i], gA[i] + ko);
            cp16(st + sB[i], gB[i] + ko);
        }
        CP_COMMIT();
    }
    CP_WAIT(2);
    __syncthreads();     // stage 0 visible to all threads

    // Load frags for (chunk 0, ks 0)
    {
        const uint32_t aB = sbase + a_off;
        const uint32_t bB = sbase + b_off;
        #pragma unroll
        for (int mf = 0; mf < 4; mf++) LDSM_X4(fa[0][mf], aB + mf * (16 * ROW_B));
        #pragma unroll
        for (int np = 0; np < 4; np++) LDSM_X4(fb[0][np], bB + np * (16 * ROW_B));
    }

    for (int c = 0; c < NK; c++) {
        const uint32_t stg = sbase + (c & (STAGES - 1)) * STAGE_B;

        // ---- ks 0: prefetch (c, ks1) frags, issue cp.async for stage c+3,
        //            then run ks0 MMAs (cover the LDSM + LSU latency) ----
        {
            const uint32_t aB = stg + a_off + 32;   // ks1 halves: +16 cols
            const uint32_t bB = stg + b_off + 32;
            #pragma unroll
            for (int mf = 0; mf < 4; mf++) LDSM_X4(fa[1][mf], aB + mf * (16 * ROW_B));
            #pragma unroll
            for (int np = 0; np < 4; np++) LDSM_X4(fb[1][np], bB + np * (16 * ROW_B));
        }
        if (c + STAGES - 1 < NK) {
            const uint32_t st = sbase + ((c + STAGES - 1) & (STAGES - 1)) * STAGE_B;
            const int ko = (c + STAGES - 1) * 32;
            #pragma unroll
            for (int i = 0; i < 4; i++) {
                cp16(st + sA[i], gA[i] + ko);
                cp16(st + sB[i], gB[i] + ko);
            }
            CP_COMMIT();
        }
        #pragma unroll
        for (int mf = 0; mf < 4; mf++)
            #pragma unroll
            for (int nf = 0; nf < 8; nf++)
                MMA16816(acc[mf][nf], fa[0][mf],
                         fb[0][nf >> 1][(nf & 1) * 2], fb[0][nf >> 1][(nf & 1) * 2 + 1]);

        // ---- ks 1: advance smem stage, prefetch (c+1, ks0) frags,
        //            then run ks1 MMAs ----
        if (c + 1 < NK) {
            if (c <= NK - 4)       CP_WAIT(2);
            else if (c == NK - 3)  CP_WAIT(1);
            else                   CP_WAIT(0);
            __syncthreads();   // stage c+1 visible; buffer (c+1+3)%4 free for next prefetch
            const uint32_t nstg = sbase + ((c + 1) & (STAGES - 1)) * STAGE_B;
            const uint32_t aB = nstg + a_off;
            const uint32_t bB = nstg + b_off;
            #pragma unroll
            for (int mf = 0; mf < 4; mf++) LDSM_X4(fa[0][mf], aB + mf * (16 * ROW_B));
            #pragma unroll
            for (int np = 0; np < 4; np++) LDSM_X4(fb[0][np], bB + np * (16 * ROW_B));
        }
        #pragma unroll
        for (int mf = 0; mf < 4; mf++)
            #pragma unroll
            for (int nf = 0; nf < 8; nf++)
                MMA16816(acc[mf][nf], fa[1][mf],
                         fb[1][nf >> 1][(nf & 1) * 2], fb[1][nf >> 1][(nf & 1) * 2 + 1]);
    }

    // Epilogue: bias + store (half2 or float2)
    const int r0 = m0 + wm * 64 + (L >> 2);
    const int cb = n0 + wn * 64 + (L & 3) * 2;
    #pragma unroll
    for (int nf = 0; nf < 8; nf++) {
        const int col = cb + nf * 8;
        const float bx = __ldg(bias + col);
        const float by = __ldg(bias + col + 1);
        #pragma unroll
        for (int mf = 0; mf < 4; mf++) {
            const int ra = r0 + mf * 16;
            const int rb = ra + 8;
            if (HALF_OUT) {
                __half* C = (__half*)Cout;
                __half2 h0 = __floats2half2_rn(acc[mf][nf][0] + bx, acc[mf][nf][1] + by);
                __half2 h1 = __floats2half2_rn(acc[mf][nf][2] + bx, acc[mf][nf][3] + by);
                *reinterpret_cast<__half2*>(C + (size_t)ra * N + col) = h0;
                *reinterpret_cast<__half2*>(C + (size_t)rb * N + col) = h1;
            } else {
                float* C = (float*)Cout;
                float2 f0 = make_float2(acc[mf][nf][0] + bx, acc[mf][nf][1] + by);
                float2 f1 = make_float2(acc[mf][nf][2] + bx, acc[mf][nf][3] + by);
                *reinterpret_cast<float2*>(C + (size_t)ra * N + col) = f0;
                *reinterpret_cast<float2*>(C + (size_t)rb * N + col) = f1;
            }
        }
    }
}

// ---------------------------------------------------------------------------
// fp32 -> fp16 convert (8 elems/thread, coalesced)
// ---------------------------------------------------------------------------
__global__ __launch_bounds__(256)
void split_kernel(const float* __restrict__ in, __half* __restrict__ out)
{
    const int i = blockIdx.x * 256 + threadIdx.x;
    const float4* in4 = reinterpret_cast<const float4*>(in);
    float4 a = in4[2 * i], b = in4[2 * i + 1];
    float v[8] = {a.x, a.y, a.z, a.w, b.x, b.y, b.z, b.w};
    __half h[8];
    #pragma unroll
    for (int j = 0; j < 8; j++) h[j] = __float2half_rn(v[j]);
    reinterpret_cast<uint4*>(out)[i] = *reinterpret_cast<uint4*>(h);
}

// ---------------------------------------------------------------------------
// W[K,N] fp32 -> transposed fp16 [N,K]
// ---------------------------------------------------------------------------
__global__ __launch_bounds__(256)
void wsplit_kernel(const float* __restrict__ W, __half* __restrict__ T,
                   int K, int N)
{
    __shared__ float t[32][33];
    const int n0 = blockIdx.x * 32, k0 = blockIdx.y * 32;
    const int tx = threadIdx.x & 31, ty = threadIdx.x >> 5;   // 32 x 8
    #pragma unroll
    for (int r = 0; r < 32; r += 8)
        t[ty + r][tx] = W[(size_t)(k0 + ty + r) * N + n0 + tx];
    __syncthreads();
    #pragma unroll
    for (int r = 0; r < 32; r += 8) {
        float v = t[tx][ty + r];
        T[(size_t)(n0 + ty + r) * K + k0 + tx] = __float2half_rn(v);
    }
}

// ---------------------------------------------------------------------------
// Per-token 16x16 cross-head attention, fp16 in -> fp16 out (fp32 compute).
// ---------------------------------------------------------------------------
__global__ __launch_bounds__(128)
void attn_kernel(const __half* __restrict__ qkv, __half* __restrict__ out)
{
    __shared__ float row[N_QKV];
    __shared__ float sc[NHEAD][NHEAD + 1];

    const int t = threadIdx.x;
    const size_t tok = blockIdx.x;
    const uint4* src = reinterpret_cast<const uint4*>(qkv + tok * (size_t)N_QKV);

    // Load 3072 halves -> fp32 smem (8 halves per uint4)
    for (int i = t; i < N_QKV / 8; i += 128) {
        uint4 v = src[i];
        const __half2* h = reinterpret_cast<const __half2*>(&v);
        #pragma unroll
        for (int j = 0; j < 4; j++) {
            float2 f = __half22float2(h[j]);
            row[i * 8 + j * 2 + 0] = f.x;
            row[i * 8 + j * 2 + 1] = f.y;
        }
    }
    __syncthreads();

    #pragma unroll
    for (int p = t; p < NHEAD * NHEAD; p += 128) {
        const int qh = p >> 4, kh = p & 15;
        const float* q  = row + qh * 192;
        const float* kk = row + kh * 192 + 64;
        float s = 0.0f;
        #pragma unroll
        for (int d = 0; d < HDIM; d++) s = fmaf(q[d], kk[d], s);
        sc[qh][kh] = s * 0.125f;   // 1/sqrt(64)
    }
    __syncthreads();

    if (t < NHEAD) {
        float m = sc[t][0];
        #pragma unroll
        for (int j = 1; j < NHEAD; j++) m = fmaxf(m, sc[t][j]);
        float sum = 0.0f;
        #pragma unroll
        for (int j = 0; j < NHEAD; j++) {
            float e = __expf(sc[t][j] - m);
            sc[t][j] = e; sum += e;
        }
        float inv = 1.0f / sum;
        #pragma unroll
        for (int j = 0; j < NHEAD; j++) sc[t][j] *= inv;
    }
    __syncthreads();

    const size_t ob = tok * (size_t)DDIM;
    #pragma unroll
    for (int o = t; o < DDIM; o += 128) {
        const int qh = o >> 6, d = o & 63;
        float a = 0.0f;
        #pragma unroll
        for (int kh = 0; kh < NHEAD; kh++)
            a = fmaf(sc[qh][kh], row[kh * 192 + 128 + d], a);
        out[ob + o] = __float2half_rn(a);
    }
}

// ---------------------------------------------------------------------------
extern "C" void kernel_launch(void* const* d_in, const int* in_sizes, int n_in,
                              void* d_out, int out_size)
{
    (void)in_sizes; (void)n_in; (void)out_size;
    const float* x     = (const float*)d_in[0];
    const float* W_qkv = (const float*)d_in[1];
    const float* b_qkv = (const float*)d_in[2];
    const float* W_out = (const float*)d_in[3];
    const float* b_out = (const float*)d_in[4];
    float* out = (float*)d_out;

    void *p_xh, *p_qkv, *p_ah, *p_wqh, *p_woh;
    cudaGetSymbolAddress(&p_xh,  g_xh);
    cudaGetSymbolAddress(&p_qkv, g_qkv);
    cudaGetSymbolAddress(&p_ah,  g_ah);
    cudaGetSymbolAddress(&p_wqh, g_wqh);
    cudaGetSymbolAddress(&p_woh, g_woh);

    cudaFuncSetAttribute(mma_gemm<true>,
                         cudaFuncAttributeMaxDynamicSharedMemorySize, SMEM_GEMM);
    cudaFuncSetAttribute(mma_gemm<false>,
                         cudaFuncAttributeMaxDynamicSharedMemorySize, SMEM_GEMM);

    // 1) x -> fp16
    split_kernel<<<(MTOT * DDIM) / 8 / 256, 256>>>(x, (__half*)p_xh);
    // 2) weights -> transposed fp16 [N,K]
    wsplit_kernel<<<dim3(N_QKV / 32, DDIM / 32), 256>>>(
        W_qkv, (__half*)p_wqh, DDIM, N_QKV);
    wsplit_kernel<<<dim3(DDIM / 32, DDIM / 32), 256>>>(
        W_out, (__half*)p_woh, DDIM, DDIM);
    // 3) GEMM1: qkv(fp16) = x @ W_qkv + b_qkv
    mma_gemm<true><<<dim3(N_QKV / 128, MTOT / 128), 128, SMEM_GEMM>>>(
        (const __half*)p_xh, (const __half*)p_wqh, b_qkv, p_qkv, N_QKV, DDIM);
    // 4) per-token attention (fp16 -> fp16)
    attn_kernel<<<MTOT, 128>>>((const __half*)p_qkv, (__half*)p_ah);
    // 5) GEMM2: out(fp32) = attn @ W_out + b_out
    mma_gemm<false><<<dim3(DDIM / 128, MTOT / 128), 128, SMEM_GEMM>>>(
        (const __half*)p_ah, (const __half*)p_woh, b_out, (void*)out, DDIM, DDIM);
}